// round 13
// baseline (speedup 1.0000x reference)
#include <cuda_runtime.h>
#include <cuda_bf16.h>
#include <math.h>
#include <stdint.h>

#define NB 8192
#define ND 256
#define NPOS 8
#define RS 528                 // smem row stride bytes (256 bf16 + 8 pad)
#define TILE_A (128 * RS)      // 67584
#define TILE_B (64 * RS)       // 33792
#define NTHREADS 512

__device__ __align__(16) __nv_bfloat16 g_zb[NB * ND];
__device__ float g_pSpd[4 * NB], g_pSneg[4 * NB], g_pTneg[4 * NB];
__device__ float g_pos_s[NB * NPOS], g_lse[NB];
__device__ float g_fpart[64];
__device__ float g_it;
__device__ unsigned g_negmin_e, g_negmax_e, g_pvmin_e, g_pvmax_e;

__device__ __forceinline__ unsigned encf(float f) {
    unsigned u = __float_as_uint(f);
    return (u & 0x80000000u) ? ~u : (u | 0x80000000u);
}
__device__ __forceinline__ float decf2(unsigned e) {
    unsigned u = (e & 0x80000000u) ? (e ^ 0x80000000u) : ~e;
    return __uint_as_float(u);
}

#define CP16(s, g)  asm volatile("cp.async.cg.shared.global [%0], [%1], 16;" :: "r"(s), "l"(g))
#define CP_COMMIT() asm volatile("cp.async.commit_group;" ::: "memory")
#define CP_WAIT(n)  asm volatile("cp.async.wait_group %0;" :: "n"(n) : "memory")

__device__ __forceinline__ uint32_t smem_u32(const void* p) {
    uint32_t a;
    asm("{ .reg .u64 t; cvta.to.shared.u64 t, %1; cvt.u32.u64 %0, t; }" : "=r"(a) : "l"(p));
    return a;
}

#define LDSM4(r0, r1, r2, r3, a) \
    asm volatile("ldmatrix.sync.aligned.m8n8.x4.shared.b16 {%0,%1,%2,%3}, [%4];" \
        : "=r"(r0), "=r"(r1), "=r"(r2), "=r"(r3) : "r"(a))

#define MMA(d, A0, A1, A2, A3, B0, B1) \
    asm volatile("mma.sync.aligned.m16n8k16.row.col.f32.bf16.bf16.f32 " \
        "{%0,%1,%2,%3},{%4,%5,%6,%7},{%8,%9},{%0,%1,%2,%3};" \
        : "+f"((d)[0]), "+f"((d)[1]), "+f"((d)[2]), "+f"((d)[3]) \
        : "r"(A0), "r"(A1), "r"(A2), "r"(A3), "r"(B0), "r"(B1))

// ---------------- small kernels ----------------
__global__ void k_norm(const float* __restrict__ emb, const float* __restrict__ temp) {
    int row = blockIdx.x, t = threadIdx.x;
    if (row == 0 && t == 0) {
        float sp = log1pf(expf(temp[0]));
        g_it = 1.0f / sp;
        g_negmin_e = 0xFFFFFFFFu; g_negmax_e = 0u;
        g_pvmin_e = 0xFFFFFFFFu;  g_pvmax_e = 0u;
    }
    float x = emb[row * ND + t];
    float s = x * x;
    #pragma unroll
    for (int o = 16; o > 0; o >>= 1) s += __shfl_xor_sync(0xFFFFFFFFu, s, o);
    __shared__ float ws[8];
    if ((t & 31) == 0) ws[t >> 5] = s;
    __syncthreads();
    float tot = 0.f;
    #pragma unroll
    for (int i = 0; i < 8; i++) tot += ws[i];
    g_zb[row * ND + t] = __float2bfloat16(x / fmaxf(sqrtf(tot), 1e-12f));
}

__global__ void k_pvminmax(const float* __restrict__ pv) {
    int i = blockIdx.x * blockDim.x + threadIdx.x;
    float v = pv[i], mn = v, mx = v;
    #pragma unroll
    for (int o = 16; o > 0; o >>= 1) {
        mn = fminf(mn, __shfl_xor_sync(0xFFFFFFFFu, mn, o));
        mx = fmaxf(mx, __shfl_xor_sync(0xFFFFFFFFu, mx, o));
    }
    if ((threadIdx.x & 31) == 0) { atomicMin(&g_pvmin_e, encf(mn)); atomicMax(&g_pvmax_e, encf(mx)); }
}

// ---------------- fused GEMM (A-resident, pipelined epilogue) ----------------
__device__ __forceinline__ void load_A(uint32_t sdst, const __nv_bfloat16* z, int tid) {
    const char* g = (const char*)z;
    #pragma unroll
    for (int i = 0; i < 8; i++) {
        int seg = tid + i * NTHREADS;          // 4096 16B segments
        int row = seg >> 5, c16 = seg & 31;
        CP16(sdst + row * RS + c16 * 16, g + row * 512 + c16 * 16);
    }
}
__device__ __forceinline__ void load_B(uint32_t sdst, const __nv_bfloat16* z, int tid) {
    const char* g = (const char*)z;
    #pragma unroll
    for (int i = 0; i < 4; i++) {
        int seg = tid + i * NTHREADS;          // 2048 16B segments (64 rows)
        int row = seg >> 5, c16 = seg & 31;
        CP16(sdst + row * RS + c16 * 16, g + row * 512 + c16 * 16);
    }
}

__global__ void __launch_bounds__(NTHREADS, 1) k_sim() {
    extern __shared__ __align__(16) char smem[];
    const int tid = threadIdx.x, w = tid >> 5, lane = tid & 31;
    const int bc = blockIdx.x;                 // 0..1 : 4096-col chunk
    const int bm = blockIdx.y;                 // 0..63: 128-row stripe
    const int wr = w & 7, wc = w >> 3;         // 16-row band (0..7), 32-col half (0..1)
    const uint32_t sbase = smem_u32(smem);
    const uint32_t sA = sbase;
    uint32_t sB[3] = { sbase + TILE_A, sbase + TILE_A + TILE_B, sbase + TILE_A + 2 * TILE_B };

    load_A(sA, g_zb + (size_t)(bm * 128) * ND, tid);
    CP_COMMIT();
    load_B(sB[0], g_zb + (size_t)(bc * 4096) * ND, tid);
    CP_COMMIT();
    load_B(sB[1], g_zb + (size_t)(bc * 4096 + 64) * ND, tid);
    CP_COMMIT();

    const float it = g_it;
    const int rowbase = bm * 128 + wr * 16;
    const uint32_t offA = (uint32_t)(wr * 16 + (lane & 15)) * RS + (uint32_t)(lane >> 4) * 16;
    const uint32_t offB = (uint32_t)(wc * 32 + ((lane >> 4) & 1) * 8 + (lane & 7)) * RS
                        + (uint32_t)((lane >> 3) & 1) * 16;

    // hoist A fragments (constant across all B tiles)
    CP_WAIT(2);
    __syncthreads();
    uint32_t a_frag[16][4];
    #pragma unroll
    for (int kk = 0; kk < 16; kk++)
        LDSM4(a_frag[kk][0], a_frag[kk][1], a_frag[kk][2], a_frag[kk][3],
              sA + offA + (uint32_t)kk * 32);

    float spd[2], sng[2], tng[2];
    #pragma unroll
    for (int h = 0; h < 2; h++) { spd[h] = 0.f; sng[h] = 0.f; tng[h] = 0.f; }
    float mn = 1e30f, mx = -1e30f;

    float acc[2][4][4];
    int cur = 0;

    for (int t = 0; t < 64; t++) {
        CP_WAIT(1);
        __syncthreads();
        if (t + 2 < 64)
            load_B(sB[(t + 2) % 3], g_zb + (size_t)(bc * 4096 + (t + 2) * 64) * ND, tid);
        CP_COMMIT();

        const uint32_t sBt = sB[t % 3];
        #pragma unroll
        for (int n = 0; n < 4; n++)
            #pragma unroll
            for (int q = 0; q < 4; q++) acc[cur][n][q] = 0.f;

        #pragma unroll
        for (int kk = 0; kk < 16; kk++) {
            uint32_t b0[4], b1[4];
            #pragma unroll
            for (int p = 0; p < 2; p++)
                LDSM4(b0[2 * p], b1[2 * p], b0[2 * p + 1], b1[2 * p + 1],
                      sBt + offB + (uint32_t)p * (16 * RS) + (uint32_t)kk * 32);
            #pragma unroll
            for (int n = 0; n < 4; n++)
                MMA(acc[cur][n], a_frag[kk][0], a_frag[kk][1], a_frag[kk][2], a_frag[kk][3],
                    b0[n], b1[n]);
        }

        // ---- epilogue for PREVIOUS tile (overlaps this tile's HMMA drain) ----
        if (t > 0) {
            const int tp = t - 1;
            const int colbase = bc * 4096 + tp * 64 + wc * 32 + (lane & 3) * 2;
            #pragma unroll
            for (int n = 0; n < 4; n++) {
                #pragma unroll
                for (int h = 0; h < 2; h++) {
                    int row = rowbase + (lane >> 2) + h * 8;
                    #pragma unroll
                    for (int q = 0; q < 2; q++) {
                        int col = colbase + n * 8 + q;
                        float v = acc[cur ^ 1][n][h * 2 + q];
                        float s = fmaf(v, it, -it);
                        float e = __expf(s);
                        unsigned d = (unsigned)(col - row) & 8191u;
                        if (d == 0u) {
                            spd[h] += e;
                        } else if (d <= 8u) {
                            spd[h] += e;
                            g_pos_s[row * NPOS + d - 1] = s;
                        } else {
                            sng[h] += e;
                            tng[h] = fmaf(s, e, tng[h]);
                            mn = fminf(mn, s); mx = fmaxf(mx, s);
                        }
                    }
                }
            }
        }
        cur ^= 1;
    }

    // final tile epilogue
    {
        const int tp = 63;
        const int colbase = bc * 4096 + tp * 64 + wc * 32 + (lane & 3) * 2;
        #pragma unroll
        for (int n = 0; n < 4; n++) {
            #pragma unroll
            for (int h = 0; h < 2; h++) {
                int row = rowbase + (lane >> 2) + h * 8;
                #pragma unroll
                for (int q = 0; q < 2; q++) {
                    int col = colbase + n * 8 + q;
                    float v = acc[cur ^ 1][n][h * 2 + q];
                    float s = fmaf(v, it, -it);
                    float e = __expf(s);
                    unsigned d = (unsigned)(col - row) & 8191u;
                    if (d == 0u) {
                        spd[h] += e;
                    } else if (d <= 8u) {
                        spd[h] += e;
                        g_pos_s[row * NPOS + d - 1] = s;
                    } else {
                        sng[h] += e;
                        tng[h] = fmaf(s, e, tng[h]);
                        mn = fminf(mn, s); mx = fmaxf(mx, s);
                    }
                }
            }
        }
    }

    // reduce the 4 lanes (lane&3) sharing each row
    const int sidx = bc * 2 + wc;
    #pragma unroll
    for (int h = 0; h < 2; h++) {
        float a0 = spd[h], a1 = sng[h], a2 = tng[h];
        a0 += __shfl_down_sync(0xFFFFFFFFu, a0, 2, 4);
        a0 += __shfl_down_sync(0xFFFFFFFFu, a0, 1, 4);
        a1 += __shfl_down_sync(0xFFFFFFFFu, a1, 2, 4);
        a1 += __shfl_down_sync(0xFFFFFFFFu, a1, 1, 4);
        a2 += __shfl_down_sync(0xFFFFFFFFu, a2, 2, 4);
        a2 += __shfl_down_sync(0xFFFFFFFFu, a2, 1, 4);
        if ((lane & 3) == 0) {
            int row = rowbase + (lane >> 2) + h * 8;
            g_pSpd [sidx * NB + row] = a0;
            g_pSneg[sidx * NB + row] = a1;
            g_pTneg[sidx * NB + row] = a2;
        }
    }
    #pragma unroll
    for (int o = 16; o > 0; o >>= 1) {
        mn = fminf(mn, __shfl_xor_sync(0xFFFFFFFFu, mn, o));
        mx = fmaxf(mx, __shfl_xor_sync(0xFFFFFFFFu, mx, o));
    }
    if (lane == 0) { atomicMin(&g_negmin_e, encf(mn)); atomicMax(&g_negmax_e, encf(mx)); }
}

__global__ void k_lse() {
    int i = blockIdx.x * blockDim.x + threadIdx.x;
    float spd = 0.f, sn = 0.f, tn = 0.f;
    #pragma unroll
    for (int t = 0; t < 4; t++) {
        spd += g_pSpd [t * NB + i];
        sn  += g_pSneg[t * NB + i];
        tn  += g_pTneg[t * NB + i];
    }
    float nmin = decf2(g_negmin_e), nmax = decf2(g_negmax_e);
    float a = 1.0f / (nmax - nmin + 1e-8f);
    float b = 1.0f - nmin * a;
    g_lse[i] = logf(spd + a * tn + b * sn);
}

__global__ void k_final1(const float* __restrict__ pv) {
    const int tid = threadIdx.x, b = blockIdx.x;      // 64 blocks x 256 threads
    float vmin = decf2(g_pvmin_e), vmax = decf2(g_pvmax_e);
    float wmin = 1.0f - vmax, wmax = 1.0f - vmin;
    float inv = 1.0f / (wmax - wmin + 1e-8f);
    float local = 0.f;
    int base = b * 1024;
    for (int k = tid; k < 1024; k += 256) {
        int idx = base + k;
        float pw = ((1.0f - pv[idx]) - wmin) * inv;
        local += (g_pos_s[idx] - g_lse[idx >> 3]) * pw;
    }
    __shared__ float red[256];
    red[tid] = local;
    __syncthreads();
    for (int s = 128; s > 0; s >>= 1) {
        if (tid < s) red[tid] += red[tid + s];
        __syncthreads();
    }
    if (tid == 0) g_fpart[b] = red[0];
}

__global__ void k_final2(float* __restrict__ out) {
    float s = 0.f;
    #pragma unroll
    for (int i = 0; i < 64; i++) s += g_fpart[i];
    out[0] = -s * (1.0f / (float)(NB * NPOS));
}

// ---------------- launch ----------------
extern "C" void kernel_launch(void* const* d_in, const int* in_sizes, int n_in,
                              void* d_out, int out_size) {
    const float* emb  = (const float*)d_in[0];
    const float* pv   = (const float*)d_in[1];
    const float* temp = (const float*)d_in[2];
    float* out = (float*)d_out;

    const int SMEM = TILE_A + 3 * TILE_B;      // 168960 B
    cudaFuncSetAttribute(k_sim, cudaFuncAttributeMaxDynamicSharedMemorySize, SMEM);

    k_norm<<<NB, ND>>>(emb, temp);
    k_pvminmax<<<(NB * NPOS) / 1024, 1024>>>(pv);
    dim3 grid(2, 64);
    k_sim<<<grid, NTHREADS, SMEM>>>();
    k_lse<<<NB / 256, 256>>>();
    k_final1<<<64, 256>>>(pv);
    k_final2<<<1, 1>>>(out);
}

// round 14
// speedup vs baseline: 1.4737x; 1.4737x over previous
#include <cuda_runtime.h>
#include <cuda_bf16.h>
#include <math.h>
#include <stdint.h>

#define NB 8192
#define ND 256
#define NPOS 8
#define RS 528                 // smem row stride bytes (256 bf16 + 8 pad)
#define TILE_A (128 * RS)      // 67584
#define NTHREADS 512
#define NSLOT 320              // 64 transposed slots + 256 row slots

__device__ __align__(16) __nv_bfloat16 g_zb[NB * ND];
__device__ float g_pSpd[NSLOT * NB], g_pSneg[NSLOT * NB], g_pTneg[NSLOT * NB];
__device__ float g_pos_s[NB * NPOS], g_lse[NB];
__device__ float g_fpart[64];
__device__ float g_it;
__device__ unsigned g_negmin_e, g_negmax_e, g_pvmin_e, g_pvmax_e;

__device__ __forceinline__ unsigned encf(float f) {
    unsigned u = __float_as_uint(f);
    return (u & 0x80000000u) ? ~u : (u | 0x80000000u);
}
__device__ __forceinline__ float decf2(unsigned e) {
    unsigned u = (e & 0x80000000u) ? (e ^ 0x80000000u) : ~e;
    return __uint_as_float(u);
}

#define CP16(s, g)  asm volatile("cp.async.cg.shared.global [%0], [%1], 16;" :: "r"(s), "l"(g))
#define CP_COMMIT() asm volatile("cp.async.commit_group;" ::: "memory")
#define CP_WAIT(n)  asm volatile("cp.async.wait_group %0;" :: "n"(n) : "memory")

__device__ __forceinline__ uint32_t smem_u32(const void* p) {
    uint32_t a;
    asm("{ .reg .u64 t; cvta.to.shared.u64 t, %1; cvt.u32.u64 %0, t; }" : "=r"(a) : "l"(p));
    return a;
}

#define LDSM4(r0, r1, r2, r3, a) \
    asm volatile("ldmatrix.sync.aligned.m8n8.x4.shared.b16 {%0,%1,%2,%3}, [%4];" \
        : "=r"(r0), "=r"(r1), "=r"(r2), "=r"(r3) : "r"(a))

#define MMA(d, A0, A1, A2, A3, B0, B1) \
    asm volatile("mma.sync.aligned.m16n8k16.row.col.f32.bf16.bf16.f32 " \
        "{%0,%1,%2,%3},{%4,%5,%6,%7},{%8,%9},{%0,%1,%2,%3};" \
        : "+f"((d)[0]), "+f"((d)[1]), "+f"((d)[2]), "+f"((d)[3]) \
        : "r"(A0), "r"(A1), "r"(A2), "r"(A3), "r"(B0), "r"(B1))

// ---------------- small kernels ----------------
__global__ void k_zero() {
    int i = blockIdx.x * blockDim.x + threadIdx.x;   // NSLOT*NB total
    g_pSpd[i] = 0.f; g_pSneg[i] = 0.f; g_pTneg[i] = 0.f;
}

__global__ void k_norm(const float* __restrict__ emb, const float* __restrict__ temp) {
    int row = blockIdx.x, t = threadIdx.x;
    if (row == 0 && t == 0) {
        float sp = log1pf(expf(temp[0]));
        g_it = 1.0f / sp;
        g_negmin_e = 0xFFFFFFFFu; g_negmax_e = 0u;
        g_pvmin_e = 0xFFFFFFFFu;  g_pvmax_e = 0u;
    }
    float x = emb[row * ND + t];
    float s = x * x;
    #pragma unroll
    for (int o = 16; o > 0; o >>= 1) s += __shfl_xor_sync(0xFFFFFFFFu, s, o);
    __shared__ float ws[8];
    if ((t & 31) == 0) ws[t >> 5] = s;
    __syncthreads();
    float tot = 0.f;
    #pragma unroll
    for (int i = 0; i < 8; i++) tot += ws[i];
    g_zb[row * ND + t] = __float2bfloat16(x / fmaxf(sqrtf(tot), 1e-12f));
}

__global__ void k_pvminmax(const float* __restrict__ pv) {
    int i = blockIdx.x * blockDim.x + threadIdx.x;
    float v = pv[i], mn = v, mx = v;
    #pragma unroll
    for (int o = 16; o > 0; o >>= 1) {
        mn = fminf(mn, __shfl_xor_sync(0xFFFFFFFFu, mn, o));
        mx = fmaxf(mx, __shfl_xor_sync(0xFFFFFFFFu, mx, o));
    }
    if ((threadIdx.x & 31) == 0) { atomicMin(&g_pvmin_e, encf(mn)); atomicMax(&g_pvmax_e, encf(mx)); }
}

// ---------------- symmetric fused GEMM ----------------
__device__ __forceinline__ void load_panel(uint32_t sdst, const __nv_bfloat16* z, int tid) {
    const char* g = (const char*)z;
    #pragma unroll
    for (int i = 0; i < 8; i++) {
        int seg = tid + i * NTHREADS;          // 4096 16B segments
        int row = seg >> 5, c16 = seg & 31;
        CP16(sdst + row * RS + c16 * 16, g + row * 512 + c16 * 16);
    }
}

__device__ __forceinline__ void flush_rows(int Iflush, int slot, int wr, int lane,
                                           float* spd, float* sng, float* tng) {
    #pragma unroll
    for (int h = 0; h < 2; h++) {
        float a0 = spd[h], a1 = sng[h], a2 = tng[h];
        a0 += __shfl_down_sync(0xFFFFFFFFu, a0, 2, 4);
        a0 += __shfl_down_sync(0xFFFFFFFFu, a0, 1, 4);
        a1 += __shfl_down_sync(0xFFFFFFFFu, a1, 2, 4);
        a1 += __shfl_down_sync(0xFFFFFFFFu, a1, 1, 4);
        a2 += __shfl_down_sync(0xFFFFFFFFu, a2, 2, 4);
        a2 += __shfl_down_sync(0xFFFFFFFFu, a2, 1, 4);
        if ((lane & 3) == 0) {
            int row = Iflush * 128 + wr * 16 + (lane >> 2) + h * 8;
            g_pSpd [slot * NB + row] = a0;
            g_pSneg[slot * NB + row] = a1;
            g_pTneg[slot * NB + row] = a2;
        }
        spd[h] = 0.f; sng[h] = 0.f; tng[h] = 0.f;
    }
}

__global__ void __launch_bounds__(NTHREADS, 1) k_sim() {
    extern __shared__ __align__(16) char smem[];
    const int tid = threadIdx.x, w = tid >> 5, lane = tid & 31;
    const int cta = blockIdx.x;                // 128 persistent CTAs
    const int wr = w & 7, wc = w >> 3;         // 16-row band (0..7), 64-col half (0..1)
    const uint32_t sbase = smem_u32(smem);
    const uint32_t sA = sbase;
    const uint32_t sB0 = sbase + TILE_A, sB1 = sbase + 2 * TILE_A;
    float* trf = (float*)(smem + 3 * TILE_A);  // [128 cols][3 stats][8 wr]

    const int p0 = (cta * 2080) >> 7, p1 = ((cta + 1) * 2080) >> 7;

    // unrank p0 (I-major, J from I..63)
    int I = 0, base = 0;
    while (p0 >= base + (64 - I)) { base += (64 - I); I++; }
    int J = I + (p0 - base);

    load_panel(sA, g_zb + (size_t)(I * 128) * ND, tid);
    load_panel(sB0, g_zb + (size_t)(J * 128) * ND, tid);
    CP_COMMIT();

    const float it = g_it;
    const uint32_t offA = (uint32_t)(wr * 16 + (lane & 15)) * RS + (uint32_t)(lane >> 4) * 16;
    const uint32_t offB = (uint32_t)(wc * 64 + ((lane >> 4) & 1) * 8 + (lane & 7)) * RS
                        + (uint32_t)((lane >> 3) & 1) * 16;
    const int rslot = 64 + cta * 2 + wc;

    uint32_t a_frag[16][4];
    float spd[2] = {0.f, 0.f}, sng[2] = {0.f, 0.f}, tng[2] = {0.f, 0.f};
    float mn = 1e30f, mx = -1e30f;
    int prevI = -1, curbuf = 0;

    for (int p = p0; p < p1; p++) {
        CP_WAIT(0);
        __syncthreads();

        if (I != prevI) {
            if (prevI >= 0) flush_rows(prevI, rslot, wr, lane, spd, sng, tng);
            #pragma unroll
            for (int kk = 0; kk < 16; kk++)
                LDSM4(a_frag[kk][0], a_frag[kk][1], a_frag[kk][2], a_frag[kk][3],
                      sA + offA + (uint32_t)kk * 32);
            __syncthreads();               // a_frag read before sA may be overwritten
            prevI = I;
        }

        // prefetch next tile
        if (p + 1 < p1) {
            int In = I, Jn = J + 1;
            if (Jn == 64) { In = I + 1; Jn = In; }
            load_panel(curbuf ? sB0 : sB1, g_zb + (size_t)(Jn * 128) * ND, tid);
            if (In != I) load_panel(sA, g_zb + (size_t)(In * 128) * ND, tid);
            CP_COMMIT();
        }

        // ---- MMA ----
        const uint32_t sBt = curbuf ? sB1 : sB0;
        float acc[8][4];
        #pragma unroll
        for (int n = 0; n < 8; n++)
            #pragma unroll
            for (int q = 0; q < 4; q++) acc[n][q] = 0.f;
        #pragma unroll
        for (int kk = 0; kk < 16; kk++) {
            uint32_t b0[8], b1[8];
            #pragma unroll
            for (int pp = 0; pp < 4; pp++)
                LDSM4(b0[2 * pp], b1[2 * pp], b0[2 * pp + 1], b1[2 * pp + 1],
                      sBt + offB + (uint32_t)pp * (16 * RS) + (uint32_t)kk * 32);
            #pragma unroll
            for (int n = 0; n < 8; n++)
                MMA(acc[n], a_frag[kk][0], a_frag[kk][1], a_frag[kk][2], a_frag[kk][3],
                    b0[n], b1[n]);
        }

        const int colb = J * 128 + wc * 64 + (lane & 3) * 2;
        const int rowb = I * 128 + wr * 16 + (lane >> 2);

        if (I == J) {
            // ---- diagonal tile: row-side only (both orientations present) ----
            #pragma unroll
            for (int n = 0; n < 8; n++) {
                #pragma unroll
                for (int h = 0; h < 2; h++) {
                    int row = rowb + h * 8;
                    #pragma unroll
                    for (int q = 0; q < 2; q++) {
                        int col = colb + n * 8 + q;
                        float v = acc[n][h * 2 + q];
                        float s = fmaf(v, it, -it);
                        float e = __expf(s);
                        unsigned d = (unsigned)(col - row) & 8191u;
                        if (d == 0u) {
                            spd[h] += e;
                        } else if (d <= 8u) {
                            spd[h] += e;
                            g_pos_s[row * NPOS + d - 1] = s;
                        } else {
                            sng[h] += e;
                            tng[h] = fmaf(s, e, tng[h]);
                            mn = fminf(mn, s); mx = fmaxf(mx, s);
                        }
                    }
                }
            }
        } else {
            // ---- off-diagonal: row-side + transposed-side ----
            #pragma unroll
            for (int n = 0; n < 8; n++) {
                #pragma unroll
                for (int q = 0; q < 2; q++) {
                    int col = colb + n * 8 + q;
                    float tS = 0.f, tE = 0.f, tT = 0.f;
                    #pragma unroll
                    for (int h = 0; h < 2; h++) {
                        int row = rowb + h * 8;
                        float v = acc[n][h * 2 + q];
                        float s = fmaf(v, it, -it);
                        float e = __expf(s);
                        unsigned d = (unsigned)(col - row) & 8191u;
                        // row-side (row): d in [1,8] -> positive
                        if (d - 1u < 8u) {
                            spd[h] += e;
                            g_pos_s[row * NPOS + d - 1] = s;
                        } else {
                            sng[h] += e;
                            tng[h] = fmaf(s, e, tng[h]);
                        }
                        // transposed-side (col): d >= 8184 -> positive
                        if (d >= 8184u) {
                            tS += e;
                            g_pos_s[col * NPOS + (8191u - d)] = s;
                        } else {
                            tE += e;
                            tT = fmaf(s, e, tT);
                        }
                        // every off-diag s is negative for at least one side
                        mn = fminf(mn, s); mx = fmaxf(mx, s);
                    }
                    // reduce over the 8 lanes (stride 4) holding this column
                    #pragma unroll
                    for (int o = 4; o < 32; o <<= 1) {
                        tS += __shfl_xor_sync(0xFFFFFFFFu, tS, o);
                        tE += __shfl_xor_sync(0xFFFFFFFFu, tE, o);
                        tT += __shfl_xor_sync(0xFFFFFFFFu, tT, o);
                    }
                    if ((lane >> 2) == 0) {
                        int cl = wc * 64 + n * 8 + (lane & 3) * 2 + q;
                        trf[(cl * 3 + 0) * 8 + wr] = tS;
                        trf[(cl * 3 + 1) * 8 + wr] = tE;
                        trf[(cl * 3 + 2) * 8 + wr] = tT;
                    }
                }
            }
            __syncthreads();
            if (tid < 384) {
                int cl = tid / 3, st = tid % 3;
                float s8 = 0.f;
                #pragma unroll
                for (int u = 0; u < 8; u++) s8 += trf[(cl * 3 + st) * 8 + u];
                float* dst = (st == 0) ? g_pSpd : (st == 1) ? g_pSneg : g_pTneg;
                dst[I * NB + J * 128 + cl] = s8;
            }
        }

        // advance
        J++;
        if (J == 64) { I++; J = I; }
        curbuf ^= 1;
    }

    flush_rows(prevI, rslot, wr, lane, spd, sng, tng);

    #pragma unroll
    for (int o = 16; o > 0; o >>= 1) {
        mn = fminf(mn, __shfl_xor_sync(0xFFFFFFFFu, mn, o));
        mx = fmaxf(mx, __shfl_xor_sync(0xFFFFFFFFu, mx, o));
    }
    if (lane == 0) { atomicMin(&g_negmin_e, encf(mn)); atomicMax(&g_negmax_e, encf(mx)); }
}

__global__ void k_lse() {
    int i = blockIdx.x * blockDim.x + threadIdx.x;
    float spd = 0.f, sn = 0.f, tn = 0.f;
    #pragma unroll 8
    for (int t = 0; t < NSLOT; t++) {
        spd += g_pSpd [t * NB + i];
        sn  += g_pSneg[t * NB + i];
        tn  += g_pTneg[t * NB + i];
    }
    float nmin = decf2(g_negmin_e), nmax = decf2(g_negmax_e);
    float a = 1.0f / (nmax - nmin + 1e-8f);
    float b = 1.0f - nmin * a;
    g_lse[i] = logf(spd + a * tn + b * sn);
}

__global__ void k_final1(const float* __restrict__ pv) {
    const int tid = threadIdx.x, b = blockIdx.x;      // 64 blocks x 256 threads
    float vmin = decf2(g_pvmin_e), vmax = decf2(g_pvmax_e);
    float wmin = 1.0f - vmax, wmax = 1.0f - vmin;
    float inv = 1.0f / (wmax - wmin + 1e-8f);
    float local = 0.f;
    int base = b * 1024;
    for (int k = tid; k < 1024; k += 256) {
        int idx = base + k;
        float pw = ((1.0f - pv[idx]) - wmin) * inv;
        local += (g_pos_s[idx] - g_lse[idx >> 3]) * pw;
    }
    __shared__ float red[256];
    red[tid] = local;
    __syncthreads();
    for (int s = 128; s > 0; s >>= 1) {
        if (tid < s) red[tid] += red[tid + s];
        __syncthreads();
    }
    if (tid == 0) g_fpart[b] = red[0];
}

__global__ void k_final2(float* __restrict__ out) {
    float s = 0.f;
    #pragma unroll
    for (int i = 0; i < 64; i++) s += g_fpart[i];
    out[0] = -s * (1.0f / (float)(NB * NPOS));
}

// ---------------- launch ----------------
extern "C" void kernel_launch(void* const* d_in, const int* in_sizes, int n_in,
                              void* d_out, int out_size) {
    const float* emb  = (const float*)d_in[0];
    const float* pv   = (const float*)d_in[1];
    const float* temp = (const float*)d_in[2];
    float* out = (float*)d_out;

    const int SMEM = 3 * TILE_A + 128 * 3 * 8 * 4;   // 202752 + 12288 = 215040
    cudaFuncSetAttribute(k_sim, cudaFuncAttributeMaxDynamicSharedMemorySize, SMEM);

    k_zero<<<(NSLOT * NB) / 1024, 1024>>>();
    k_norm<<<NB, ND>>>(emb, temp);
    k_pvminmax<<<(NB * NPOS) / 1024, 1024>>>(pv);
    k_sim<<<128, NTHREADS, SMEM>>>();
    k_lse<<<NB / 256, 256>>>();
    k_final1<<<64, 256>>>(pv);
    k_final2<<<1, 1>>>(out);
}

// round 15
// speedup vs baseline: 1.7624x; 1.1959x over previous
#include <cuda_runtime.h>
#include <cuda_bf16.h>
#include <math.h>
#include <stdint.h>

#define NB 8192
#define ND 256
#define NPOS 8
#define RS 528                 // smem row stride bytes (256 bf16 + 8 pad)
#define TILE_A (128 * RS)      // 67584
#define NTHREADS 512
#define NSLOT 76               // 64 transposed slots + 12 row slots

__device__ __align__(16) __nv_bfloat16 g_zb[NB * ND];
__device__ float g_pSpd[NSLOT * NB], g_pSneg[NSLOT * NB], g_pTneg[NSLOT * NB];
__device__ float g_pos_s[NB * NPOS];
__device__ float g_fpart[32];
__device__ float g_it;
__device__ unsigned g_negmin_e, g_negmax_e, g_pvmin_e, g_pvmax_e;

__device__ __forceinline__ unsigned encf(float f) {
    unsigned u = __float_as_uint(f);
    return (u & 0x80000000u) ? ~u : (u | 0x80000000u);
}
__device__ __forceinline__ float decf2(unsigned e) {
    unsigned u = (e & 0x80000000u) ? (e ^ 0x80000000u) : ~e;
    return __uint_as_float(u);
}

#define CP16(s, g)  asm volatile("cp.async.cg.shared.global [%0], [%1], 16;" :: "r"(s), "l"(g))
#define CP_COMMIT() asm volatile("cp.async.commit_group;" ::: "memory")
#define CP_WAIT(n)  asm volatile("cp.async.wait_group %0;" :: "n"(n) : "memory")

__device__ __forceinline__ uint32_t smem_u32(const void* p) {
    uint32_t a;
    asm("{ .reg .u64 t; cvta.to.shared.u64 t, %1; cvt.u32.u64 %0, t; }" : "=r"(a) : "l"(p));
    return a;
}

#define LDSM4(r0, r1, r2, r3, a) \
    asm volatile("ldmatrix.sync.aligned.m8n8.x4.shared.b16 {%0,%1,%2,%3}, [%4];" \
        : "=r"(r0), "=r"(r1), "=r"(r2), "=r"(r3) : "r"(a))

#define MMA(d, A0, A1, A2, A3, B0, B1) \
    asm volatile("mma.sync.aligned.m16n8k16.row.col.f32.bf16.bf16.f32 " \
        "{%0,%1,%2,%3},{%4,%5,%6,%7},{%8,%9},{%0,%1,%2,%3};" \
        : "+f"((d)[0]), "+f"((d)[1]), "+f"((d)[2]), "+f"((d)[3]) \
        : "r"(A0), "r"(A1), "r"(A2), "r"(A3), "r"(B0), "r"(B1))

// ---------------- small kernels ----------------
__global__ void k_norm(const float* __restrict__ emb, const float* __restrict__ temp) {
    int row = blockIdx.x, t = threadIdx.x;
    if (row == 0 && t == 0) {
        float sp = log1pf(expf(temp[0]));
        g_it = 1.0f / sp;
        g_negmin_e = 0xFFFFFFFFu; g_negmax_e = 0u;
        g_pvmin_e = 0xFFFFFFFFu;  g_pvmax_e = 0u;
    }
    float x = emb[row * ND + t];
    float s = x * x;
    #pragma unroll
    for (int o = 16; o > 0; o >>= 1) s += __shfl_xor_sync(0xFFFFFFFFu, s, o);
    __shared__ float ws[8];
    if ((t & 31) == 0) ws[t >> 5] = s;
    __syncthreads();
    float tot = 0.f;
    #pragma unroll
    for (int i = 0; i < 8; i++) tot += ws[i];
    g_zb[row * ND + t] = __float2bfloat16(x / fmaxf(sqrtf(tot), 1e-12f));
}

// zero the partial slots; blocks < 64 also scan pos_vals for min/max
__global__ void k_zpv(const float* __restrict__ pv) {
    int i = blockIdx.x * blockDim.x + threadIdx.x;   // NSLOT*NB total
    g_pSpd[i] = 0.f; g_pSneg[i] = 0.f; g_pTneg[i] = 0.f;
    if (i < NB * NPOS) {
        float v = pv[i], mn = v, mx = v;
        #pragma unroll
        for (int o = 16; o > 0; o >>= 1) {
            mn = fminf(mn, __shfl_xor_sync(0xFFFFFFFFu, mn, o));
            mx = fmaxf(mx, __shfl_xor_sync(0xFFFFFFFFu, mx, o));
        }
        if ((threadIdx.x & 31) == 0) { atomicMin(&g_pvmin_e, encf(mn)); atomicMax(&g_pvmax_e, encf(mx)); }
    }
}

// ---------------- symmetric fused GEMM ----------------
__device__ __forceinline__ void load_panel(uint32_t sdst, const __nv_bfloat16* z, int tid) {
    const char* g = (const char*)z;
    #pragma unroll
    for (int i = 0; i < 8; i++) {
        int seg = tid + i * NTHREADS;          // 4096 16B segments
        int row = seg >> 5, c16 = seg & 31;
        CP16(sdst + row * RS + c16 * 16, g + row * 512 + c16 * 16);
    }
}

__device__ __forceinline__ void flush_rows(int Iflush, int slot, int wr, int lane,
                                           float* spd, float* sng, float* tng) {
    #pragma unroll
    for (int h = 0; h < 2; h++) {
        float a0 = spd[h], a1 = sng[h], a2 = tng[h];
        a0 += __shfl_down_sync(0xFFFFFFFFu, a0, 2, 4);
        a0 += __shfl_down_sync(0xFFFFFFFFu, a0, 1, 4);
        a1 += __shfl_down_sync(0xFFFFFFFFu, a1, 2, 4);
        a1 += __shfl_down_sync(0xFFFFFFFFu, a1, 1, 4);
        a2 += __shfl_down_sync(0xFFFFFFFFu, a2, 2, 4);
        a2 += __shfl_down_sync(0xFFFFFFFFu, a2, 1, 4);
        if ((lane & 3) == 0) {
            int row = Iflush * 128 + wr * 16 + (lane >> 2) + h * 8;
            g_pSpd [slot * NB + row] = a0;
            g_pSneg[slot * NB + row] = a1;
            g_pTneg[slot * NB + row] = a2;
        }
        spd[h] = 0.f; sng[h] = 0.f; tng[h] = 0.f;
    }
}

__device__ __forceinline__ int row_slot(int I, int cta, int wc) {
    int bI = 64 * I - (I * (I - 1)) / 2;       // first pair index of stripe I
    int fc = (bI * 128) / 2080;                // first CTA covering stripe I
    return 64 + (cta - fc) * 2 + wc;
}

__global__ void __launch_bounds__(NTHREADS, 1) k_sim() {
    extern __shared__ __align__(16) char smem[];
    const int tid = threadIdx.x, w = tid >> 5, lane = tid & 31;
    const int cta = blockIdx.x;                // 128 persistent CTAs
    const int wr = w & 7, wc = w >> 3;         // 16-row band (0..7), 64-col half (0..1)
    const uint32_t sbase = smem_u32(smem);
    const uint32_t sA = sbase;
    const uint32_t sB0 = sbase + TILE_A, sB1 = sbase + 2 * TILE_A;
    float* trf = (float*)(smem + 3 * TILE_A);  // [128 cols][3 stats][8 wr]

    const int p0 = (cta * 2080) >> 7, p1 = ((cta + 1) * 2080) >> 7;

    // unrank p0 (I-major, J from I..63)
    int I = 0, base = 0;
    while (p0 >= base + (64 - I)) { base += (64 - I); I++; }
    int J = I + (p0 - base);

    load_panel(sA, g_zb + (size_t)(I * 128) * ND, tid);
    load_panel(sB0, g_zb + (size_t)(J * 128) * ND, tid);
    CP_COMMIT();

    const float it = g_it;
    const uint32_t offA = (uint32_t)(wr * 16 + (lane & 15)) * RS + (uint32_t)(lane >> 4) * 16;
    const uint32_t offB = (uint32_t)(wc * 64 + ((lane >> 4) & 1) * 8 + (lane & 7)) * RS
                        + (uint32_t)((lane >> 3) & 1) * 16;

    uint32_t a_frag[16][4];
    float spd[2] = {0.f, 0.f}, sng[2] = {0.f, 0.f}, tng[2] = {0.f, 0.f};
    float mn = 1e30f, mx = -1e30f;
    int prevI = -1, curbuf = 0;

    for (int p = p0; p < p1; p++) {
        CP_WAIT(0);
        __syncthreads();

        if (I != prevI) {
            if (prevI >= 0)
                flush_rows(prevI, row_slot(prevI, cta, wc), wr, lane, spd, sng, tng);
            #pragma unroll
            for (int kk = 0; kk < 16; kk++)
                LDSM4(a_frag[kk][0], a_frag[kk][1], a_frag[kk][2], a_frag[kk][3],
                      sA + offA + (uint32_t)kk * 32);
            __syncthreads();               // a_frag read before sA may be overwritten
            prevI = I;
        }

        // prefetch next tile
        if (p + 1 < p1) {
            int In = I, Jn = J + 1;
            if (Jn == 64) { In = I + 1; Jn = In; }
            load_panel(curbuf ? sB0 : sB1, g_zb + (size_t)(Jn * 128) * ND, tid);
            if (In != I) load_panel(sA, g_zb + (size_t)(In * 128) * ND, tid);
            CP_COMMIT();
        }

        // ---- MMA ----
        const uint32_t sBt = curbuf ? sB1 : sB0;
        float acc[8][4];
        #pragma unroll
        for (int n = 0; n < 8; n++)
            #pragma unroll
            for (int q = 0; q < 4; q++) acc[n][q] = 0.f;
        #pragma unroll
        for (int kk = 0; kk < 16; kk++) {
            uint32_t b0[8], b1[8];
            #pragma unroll
            for (int pp = 0; pp < 4; pp++)
                LDSM4(b0[2 * pp], b1[2 * pp], b0[2 * pp + 1], b1[2 * pp + 1],
                      sBt + offB + (uint32_t)pp * (16 * RS) + (uint32_t)kk * 32);
            #pragma unroll
            for (int n = 0; n < 8; n++)
                MMA(acc[n], a_frag[kk][0], a_frag[kk][1], a_frag[kk][2], a_frag[kk][3],
                    b0[n], b1[n]);
        }

        const int colb = J * 128 + wc * 64 + (lane & 3) * 2;
        const int rowb = I * 128 + wr * 16 + (lane >> 2);

        if (I == J) {
            // ---- diagonal tile: row-side only ----
            #pragma unroll
            for (int n = 0; n < 8; n++) {
                #pragma unroll
                for (int h = 0; h < 2; h++) {
                    int row = rowb + h * 8;
                    #pragma unroll
                    for (int q = 0; q < 2; q++) {
                        int col = colb + n * 8 + q;
                        float v = acc[n][h * 2 + q];
                        float s = fmaf(v, it, -it);
                        float e = __expf(s);
                        unsigned d = (unsigned)(col - row) & 8191u;
                        if (d == 0u) {
                            spd[h] += e;
                        } else if (d <= 8u) {
                            spd[h] += e;
                            g_pos_s[row * NPOS + d - 1] = s;
                        } else {
                            sng[h] += e;
                            tng[h] = fmaf(s, e, tng[h]);
                            mn = fminf(mn, s); mx = fmaxf(mx, s);
                        }
                    }
                }
            }
        } else {
            // ---- off-diagonal: row-side + transposed-side ----
            #pragma unroll
            for (int n = 0; n < 8; n++) {
                #pragma unroll
                for (int q = 0; q < 2; q++) {
                    int col = colb + n * 8 + q;
                    float tS = 0.f, tE = 0.f, tT = 0.f;
                    #pragma unroll
                    for (int h = 0; h < 2; h++) {
                        int row = rowb + h * 8;
                        float v = acc[n][h * 2 + q];
                        float s = fmaf(v, it, -it);
                        float e = __expf(s);
                        unsigned d = (unsigned)(col - row) & 8191u;
                        if (d - 1u < 8u) {
                            spd[h] += e;
                            g_pos_s[row * NPOS + d - 1] = s;
                        } else {
                            sng[h] += e;
                            tng[h] = fmaf(s, e, tng[h]);
                        }
                        if (d >= 8184u) {
                            tS += e;
                            g_pos_s[col * NPOS + (8191u - d)] = s;
                        } else {
                            tE += e;
                            tT = fmaf(s, e, tT);
                        }
                        mn = fminf(mn, s); mx = fmaxf(mx, s);
                    }
                    #pragma unroll
                    for (int o = 4; o < 32; o <<= 1) {
                        tS += __shfl_xor_sync(0xFFFFFFFFu, tS, o);
                        tE += __shfl_xor_sync(0xFFFFFFFFu, tE, o);
                        tT += __shfl_xor_sync(0xFFFFFFFFu, tT, o);
                    }
                    if ((lane >> 2) == 0) {
                        int cl = wc * 64 + n * 8 + (lane & 3) * 2 + q;
                        trf[(cl * 3 + 0) * 8 + wr] = tS;
                        trf[(cl * 3 + 1) * 8 + wr] = tE;
                        trf[(cl * 3 + 2) * 8 + wr] = tT;
                    }
                }
            }
            __syncthreads();
            if (tid < 384) {
                int cl = tid / 3, st = tid % 3;
                float s8 = 0.f;
                #pragma unroll
                for (int u = 0; u < 8; u++) s8 += trf[(cl * 3 + st) * 8 + u];
                float* dst = (st == 0) ? g_pSpd : (st == 1) ? g_pSneg : g_pTneg;
                dst[I * NB + J * 128 + cl] = s8;
            }
        }

        J++;
        if (J == 64) { I++; J = I; }
        curbuf ^= 1;
    }

    flush_rows(prevI, row_slot(prevI, cta, wc), wr, lane, spd, sng, tng);

    #pragma unroll
    for (int o = 16; o > 0; o >>= 1) {
        mn = fminf(mn, __shfl_xor_sync(0xFFFFFFFFu, mn, o));
        mx = fmaxf(mx, __shfl_xor_sync(0xFFFFFFFFu, mx, o));
    }
    if (lane == 0) { atomicMin(&g_negmin_e, encf(mn)); atomicMax(&g_negmax_e, encf(mx)); }
}

// lse per row + fused positive-pair contribution reduce (32 blocks x 256)
__global__ void k_lse(const float* __restrict__ pv) {
    const int tid = threadIdx.x;
    int i = blockIdx.x * 256 + tid;
    float spd = 0.f, sn = 0.f, tn = 0.f;
    #pragma unroll 4
    for (int t = 0; t < NSLOT; t++) {
        spd += g_pSpd [t * NB + i];
        sn  += g_pSneg[t * NB + i];
        tn  += g_pTneg[t * NB + i];
    }
    float nmin = decf2(g_negmin_e), nmax = decf2(g_negmax_e);
    float a = 1.0f / (nmax - nmin + 1e-8f);
    float b = 1.0f - nmin * a;
    float lse = logf(spd + a * tn + b * sn);

    float vmin = decf2(g_pvmin_e), vmax = decf2(g_pvmax_e);
    float wmin = 1.0f - vmax, wmax = 1.0f - vmin;
    float inv = 1.0f / (wmax - wmin + 1e-8f);
    float local = 0.f;
    #pragma unroll
    for (int k = 0; k < NPOS; k++) {
        int idx = i * NPOS + k;
        float pw = ((1.0f - pv[idx]) - wmin) * inv;
        local += (g_pos_s[idx] - lse) * pw;
    }
    __shared__ float red[256];
    red[tid] = local;
    __syncthreads();
    for (int s = 128; s > 0; s >>= 1) {
        if (tid < s) red[tid] += red[tid + s];
        __syncthreads();
    }
    if (tid == 0) g_fpart[blockIdx.x] = red[0];
}

__global__ void k_final2(float* __restrict__ out) {
    float s = 0.f;
    #pragma unroll
    for (int i = 0; i < 32; i++) s += g_fpart[i];
    out[0] = -s * (1.0f / (float)(NB * NPOS));
}

// ---------------- launch ----------------
extern "C" void kernel_launch(void* const* d_in, const int* in_sizes, int n_in,
                              void* d_out, int out_size) {
    const float* emb  = (const float*)d_in[0];
    const float* pv   = (const float*)d_in[1];
    const float* temp = (const float*)d_in[2];
    float* out = (float*)d_out;

    const int SMEM = 3 * TILE_A + 128 * 3 * 8 * 4;   // 202752 + 12288 = 215040
    cudaFuncSetAttribute(k_sim, cudaFuncAttributeMaxDynamicSharedMemorySize, SMEM);

    k_norm<<<NB, ND>>>(emb, temp);
    k_zpv<<<(NSLOT * NB) / 1024, 1024>>>(pv);
    k_sim<<<128, NTHREADS, SMEM>>>();
    k_lse<<<NB / 256, 256>>>(pv);
    k_final2<<<1, 1>>>(out);
}

// round 17
// speedup vs baseline: 1.9699x; 1.1178x over previous
#include <cuda_runtime.h>
#include <cuda_bf16.h>
#include <math.h>
#include <stdint.h>

#define NB 8192
#define ND 256
#define NPOS 8
#define RS 528                 // smem row stride bytes (256 bf16 + 8 pad)
#define TILE_A (128 * RS)      // 67584
#define NTHREADS 512
#define NSLOT 76               // 64 transposed slots + 12 row slots

__device__ __align__(16) __nv_bfloat16 g_zb[NB * ND];
__device__ float g_pSpd[NSLOT * NB], g_pSneg[NSLOT * NB], g_pTneg[NSLOT * NB];
__device__ float g_pos_s[NB * NPOS];
__device__ float g_fpart[256];
__device__ float g_it;
__device__ unsigned g_negmin_e, g_negmax_e, g_pvmin_e, g_pvmax_e;

__device__ __forceinline__ unsigned encf(float f) {
    unsigned u = __float_as_uint(f);
    return (u & 0x80000000u) ? ~u : (u | 0x80000000u);
}
__device__ __forceinline__ float decf2(unsigned e) {
    unsigned u = (e & 0x80000000u) ? (e ^ 0x80000000u) : ~e;
    return __uint_as_float(u);
}

#define CP16(s, g)  asm volatile("cp.async.cg.shared.global [%0], [%1], 16;" :: "r"(s), "l"(g))
#define CP_COMMIT() asm volatile("cp.async.commit_group;" ::: "memory")
#define CP_WAIT(n)  asm volatile("cp.async.wait_group %0;" :: "n"(n) : "memory")

__device__ __forceinline__ uint32_t smem_u32(const void* p) {
    uint32_t a;
    asm("{ .reg .u64 t; cvta.to.shared.u64 t, %1; cvt.u32.u64 %0, t; }" : "=r"(a) : "l"(p));
    return a;
}

#define LDSM4(r0, r1, r2, r3, a) \
    asm volatile("ldmatrix.sync.aligned.m8n8.x4.shared.b16 {%0,%1,%2,%3}, [%4];" \
        : "=r"(r0), "=r"(r1), "=r"(r2), "=r"(r3) : "r"(a))

#define MMA(d, A0, A1, A2, A3, B0, B1) \
    asm volatile("mma.sync.aligned.m16n8k16.row.col.f32.bf16.bf16.f32 " \
        "{%0,%1,%2,%3},{%4,%5,%6,%7},{%8,%9},{%0,%1,%2,%3};" \
        : "+f"((d)[0]), "+f"((d)[1]), "+f"((d)[2]), "+f"((d)[3]) \
        : "r"(A0), "r"(A1), "r"(A2), "r"(A3), "r"(B0), "r"(B1))

// ---------------- small kernels ----------------
__global__ void k_norm(const float* __restrict__ emb, const float* __restrict__ temp) {
    int row = blockIdx.x, t = threadIdx.x;
    if (row == 0 && t == 0) {
        float sp = log1pf(expf(temp[0]));
        g_it = 1.0f / sp;
        g_negmin_e = 0xFFFFFFFFu; g_negmax_e = 0u;
        g_pvmin_e = 0xFFFFFFFFu;  g_pvmax_e = 0u;
    }
    float x = emb[row * ND + t];
    float s = x * x;
    #pragma unroll
    for (int o = 16; o > 0; o >>= 1) s += __shfl_xor_sync(0xFFFFFFFFu, s, o);
    __shared__ float ws[8];
    if ((t & 31) == 0) ws[t >> 5] = s;
    __syncthreads();
    float tot = 0.f;
    #pragma unroll
    for (int i = 0; i < 8; i++) tot += ws[i];
    g_zb[row * ND + t] = __float2bfloat16(x / fmaxf(sqrtf(tot), 1e-12f));
}

// zero the partial slots; low blocks also scan pos_vals for min/max
__global__ void k_zpv(const float* __restrict__ pv) {
    int i = blockIdx.x * blockDim.x + threadIdx.x;   // NSLOT*NB total
    g_pSpd[i] = 0.f; g_pSneg[i] = 0.f; g_pTneg[i] = 0.f;
    if (i < NB * NPOS) {
        float v = pv[i], mn = v, mx = v;
        #pragma unroll
        for (int o = 16; o > 0; o >>= 1) {
            mn = fminf(mn, __shfl_xor_sync(0xFFFFFFFFu, mn, o));
            mx = fmaxf(mx, __shfl_xor_sync(0xFFFFFFFFu, mx, o));
        }
        if ((threadIdx.x & 31) == 0) { atomicMin(&g_pvmin_e, encf(mn)); atomicMax(&g_pvmax_e, encf(mx)); }
    }
}

// ---------------- symmetric fused GEMM ----------------
__device__ __forceinline__ void load_panel(uint32_t sdst, const __nv_bfloat16* z, int tid) {
    const char* g = (const char*)z;
    #pragma unroll
    for (int i = 0; i < 8; i++) {
        int seg = tid + i * NTHREADS;          // 4096 16B segments
        int row = seg >> 5, c16 = seg & 31;
        CP16(sdst + row * RS + c16 * 16, g + row * 512 + c16 * 16);
    }
}

__device__ __forceinline__ void flush_rows(int Iflush, int slot, int wr, int lane,
                                           float* spd, float* sng, float* tng) {
    #pragma unroll
    for (int h = 0; h < 2; h++) {
        float a0 = spd[h], a1 = sng[h], a2 = tng[h];
        a0 += __shfl_down_sync(0xFFFFFFFFu, a0, 2, 4);
        a0 += __shfl_down_sync(0xFFFFFFFFu, a0, 1, 4);
        a1 += __shfl_down_sync(0xFFFFFFFFu, a1, 2, 4);
        a1 += __shfl_down_sync(0xFFFFFFFFu, a1, 1, 4);
        a2 += __shfl_down_sync(0xFFFFFFFFu, a2, 2, 4);
        a2 += __shfl_down_sync(0xFFFFFFFFu, a2, 1, 4);
        if ((lane & 3) == 0) {
            int row = Iflush * 128 + wr * 16 + (lane >> 2) + h * 8;
            g_pSpd [slot * NB + row] = a0;
            g_pSneg[slot * NB + row] = a1;
            g_pTneg[slot * NB + row] = a2;
        }
        spd[h] = 0.f; sng[h] = 0.f; tng[h] = 0.f;
    }
}

__device__ __forceinline__ int row_slot(int I, int cta, int wc) {
    int bI = 64 * I - (I * (I - 1)) / 2;       // first pair index of stripe I
    int fc = (bI * 128) / 2080;                // first CTA covering stripe I
    return 64 + (cta - fc) * 2 + wc;
}

__global__ void __launch_bounds__(NTHREADS, 1) k_sim() {
    extern __shared__ __align__(16) char smem[];
    const int tid = threadIdx.x, w = tid >> 5, lane = tid & 31;
    const int cta = blockIdx.x;                // 128 persistent CTAs
    const int wr = w & 7, wc = w >> 3;         // 16-row band (0..7), 64-col half (0..1)
    const uint32_t sbase = smem_u32(smem);
    const uint32_t sA = sbase;
    const uint32_t sB0 = sbase + TILE_A, sB1 = sbase + 2 * TILE_A;
    float* trf = (float*)(smem + 3 * TILE_A);  // [128 cols][<=3 stats][8 wr]

    const int p0 = (cta * 2080) >> 7, p1 = ((cta + 1) * 2080) >> 7;

    // unrank p0 (I-major, J from I..63)
    int I = 0, base = 0;
    while (p0 >= base + (64 - I)) { base += (64 - I); I++; }
    int J = I + (p0 - base);

    load_panel(sA, g_zb + (size_t)(I * 128) * ND, tid);
    load_panel(sB0, g_zb + (size_t)(J * 128) * ND, tid);
    CP_COMMIT();

    const float it = g_it;
    const uint32_t offA = (uint32_t)(wr * 16 + (lane & 15)) * RS + (uint32_t)(lane >> 4) * 16;
    const uint32_t offB = (uint32_t)(wc * 64 + ((lane >> 4) & 1) * 8 + (lane & 7)) * RS
                        + (uint32_t)((lane >> 3) & 1) * 16;

    uint32_t a_frag[16][4];
    float spd[2] = {0.f, 0.f}, sng[2] = {0.f, 0.f}, tng[2] = {0.f, 0.f};
    float mn = 1e30f, mx = -1e30f;
    int prevI = -1, curbuf = 0;

    for (int p = p0; p < p1; p++) {
        CP_WAIT(0);
        __syncthreads();

        if (I != prevI) {
            if (prevI >= 0)
                flush_rows(prevI, row_slot(prevI, cta, wc), wr, lane, spd, sng, tng);
            #pragma unroll
            for (int kk = 0; kk < 16; kk++)
                LDSM4(a_frag[kk][0], a_frag[kk][1], a_frag[kk][2], a_frag[kk][3],
                      sA + offA + (uint32_t)kk * 32);
            __syncthreads();               // a_frag read before sA may be overwritten
            prevI = I;
        }

        // prefetch next tile
        if (p + 1 < p1) {
            int In = I, Jn = J + 1;
            if (Jn == 64) { In = I + 1; Jn = In; }
            load_panel(curbuf ? sB0 : sB1, g_zb + (size_t)(Jn * 128) * ND, tid);
            if (In != I) load_panel(sA, g_zb + (size_t)(In * 128) * ND, tid);
            CP_COMMIT();
        }

        // ---- MMA ----
        const uint32_t sBt = curbuf ? sB1 : sB0;
        float acc[8][4];
        #pragma unroll
        for (int n = 0; n < 8; n++)
            #pragma unroll
            for (int q = 0; q < 4; q++) acc[n][q] = 0.f;
        #pragma unroll
        for (int kk = 0; kk < 16; kk++) {
            uint32_t b0[8], b1[8];
            #pragma unroll
            for (int pp = 0; pp < 4; pp++)
                LDSM4(b0[2 * pp], b1[2 * pp], b0[2 * pp + 1], b1[2 * pp + 1],
                      sBt + offB + (uint32_t)pp * (16 * RS) + (uint32_t)kk * 32);
            #pragma unroll
            for (int n = 0; n < 8; n++)
                MMA(acc[n], a_frag[kk][0], a_frag[kk][1], a_frag[kk][2], a_frag[kk][3],
                    b0[n], b1[n]);
        }

        const int colb = J * 128 + wc * 64 + (lane & 3) * 2;
        const int rowb = I * 128 + wr * 16 + (lane >> 2);
        const bool near = (J == I + 1) || (I == 0 && J == 63);

        if (I == J) {
            // ---- diagonal tile: row-side only ----
            #pragma unroll
            for (int n = 0; n < 8; n++) {
                #pragma unroll
                for (int h = 0; h < 2; h++) {
                    int row = rowb + h * 8;
                    #pragma unroll
                    for (int q = 0; q < 2; q++) {
                        int col = colb + n * 8 + q;
                        float v = acc[n][h * 2 + q];
                        float s = fmaf(v, it, -it);
                        float e = __expf(s);
                        unsigned d = (unsigned)(col - row) & 8191u;
                        if (d == 0u) {
                            spd[h] += e;
                        } else if (d <= 8u) {
                            spd[h] += e;
                            g_pos_s[row * NPOS + d - 1] = s;
                        } else {
                            sng[h] += e;
                            tng[h] = fmaf(s, e, tng[h]);
                            mn = fminf(mn, s); mx = fmaxf(mx, s);
                        }
                    }
                }
            }
        } else if (near) {
            // ---- near tiles (J=I+1 or wrap): full dual-side classification ----
            #pragma unroll
            for (int n = 0; n < 8; n++) {
                #pragma unroll
                for (int q = 0; q < 2; q++) {
                    int col = colb + n * 8 + q;
                    float tS = 0.f, tE = 0.f, tT = 0.f;
                    #pragma unroll
                    for (int h = 0; h < 2; h++) {
                        int row = rowb + h * 8;
                        float v = acc[n][h * 2 + q];
                        float s = fmaf(v, it, -it);
                        float e = __expf(s);
                        unsigned d = (unsigned)(col - row) & 8191u;
                        if (d - 1u < 8u) {
                            spd[h] += e;
                            g_pos_s[row * NPOS + d - 1] = s;
                        } else {
                            sng[h] += e;
                            tng[h] = fmaf(s, e, tng[h]);
                        }
                        if (d >= 8184u) {
                            tS += e;
                            g_pos_s[col * NPOS + (8191u - d)] = s;
                        } else {
                            tE += e;
                            tT = fmaf(s, e, tT);
                        }
                        mn = fminf(mn, s); mx = fmaxf(mx, s);
                    }
                    #pragma unroll
                    for (int o = 4; o < 32; o <<= 1) {
                        tS += __shfl_xor_sync(0xFFFFFFFFu, tS, o);
                        tE += __shfl_xor_sync(0xFFFFFFFFu, tE, o);
                        tT += __shfl_xor_sync(0xFFFFFFFFu, tT, o);
                    }
                    if ((lane >> 2) == 0) {
                        int cl = wc * 64 + n * 8 + (lane & 3) * 2 + q;
                        trf[(cl * 3 + 0) * 8 + wr] = tS;
                        trf[(cl * 3 + 1) * 8 + wr] = tE;
                        trf[(cl * 3 + 2) * 8 + wr] = tT;
                    }
                }
            }
            __syncthreads();
            if (tid < 384) {
                int cl = tid / 3, st = tid % 3;
                float s8 = 0.f;
                #pragma unroll
                for (int u = 0; u < 8; u++) s8 += trf[(cl * 3 + st) * 8 + u];
                float* dst = (st == 0) ? g_pSpd : (st == 1) ? g_pSneg : g_pTneg;
                dst[I * NB + J * 128 + cl] = s8;
            }
        } else {
            // ---- far tiles (94%): pure negatives, branch-free ----
            #pragma unroll
            for (int n = 0; n < 8; n++) {
                #pragma unroll
                for (int q = 0; q < 2; q++) {
                    float v0 = acc[n][q], v1 = acc[n][2 + q];
                    float s0 = fmaf(v0, it, -it), s1 = fmaf(v1, it, -it);
                    float e0 = __expf(s0), e1 = __expf(s1);
                    sng[0] += e0; tng[0] = fmaf(s0, e0, tng[0]);
                    sng[1] += e1; tng[1] = fmaf(s1, e1, tng[1]);
                    mn = fminf(mn, fminf(s0, s1));
                    mx = fmaxf(mx, fmaxf(s0, s1));
                    float tE = e0 + e1;
                    float tT = fmaf(s0, e0, s1 * e1);
                    #pragma unroll
                    for (int o = 4; o < 32; o <<= 1) {
                        tE += __shfl_xor_sync(0xFFFFFFFFu, tE, o);
                        tT += __shfl_xor_sync(0xFFFFFFFFu, tT, o);
                    }
                    if ((lane >> 2) == 0) {
                        int cl = wc * 64 + n * 8 + (lane & 3) * 2 + q;
                        trf[(cl * 2 + 0) * 8 + wr] = tE;
                        trf[(cl * 2 + 1) * 8 + wr] = tT;
                    }
                }
            }
            __syncthreads();
            if (tid < 256) {
                int cl = tid >> 1, st = tid & 1;
                float s8 = 0.f;
                #pragma unroll
                for (int u = 0; u < 8; u++) s8 += trf[(cl * 2 + st) * 8 + u];
                float* dst = st ? g_pTneg : g_pSneg;
                dst[I * NB + J * 128 + cl] = s8;   // g_pSpd slot stays 0 from init
            }
        }

        J++;
        if (J == 64) { I++; J = I; }
        curbuf ^= 1;
    }

    flush_rows(prevI, row_slot(prevI, cta, wc), wr, lane, spd, sng, tng);

    #pragma unroll
    for (int o = 16; o > 0; o >>= 1) {
        mn = fminf(mn, __shfl_xor_sync(0xFFFFFFFFu, mn, o));
        mx = fmaxf(mx, __shfl_xor_sync(0xFFFFFFFFu, mx, o));
    }
    if (lane == 0) { atomicMin(&g_negmin_e, encf(mn)); atomicMax(&g_negmax_e, encf(mx)); }
}

// lse per row + fused positive reduce; 8 threads per row (256 blocks x 256 thr)
__global__ void k_lse(const float* __restrict__ pv) {
    const int tid = threadIdx.x;
    const int sub = tid & 7;                   // slot-chunk / positive index
    const int i = blockIdx.x * 32 + (tid >> 3);
    float spd = 0.f, sn = 0.f, tn = 0.f;
    for (int t = sub; t < NSLOT; t += 8) {
        spd += g_pSpd [t * NB + i];
        sn  += g_pSneg[t * NB + i];
        tn  += g_pTneg[t * NB + i];
    }
    #pragma unroll
    for (int o = 4; o > 0; o >>= 1) {
        spd += __shfl_down_sync(0xFFFFFFFFu, spd, o, 8);
        sn  += __shfl_down_sync(0xFFFFFFFFu, sn,  o, 8);
        tn  += __shfl_down_sync(0xFFFFFFFFu, tn,  o, 8);
    }
    float lse = 0.f;
    if (sub == 0) {
        float nmin = decf2(g_negmin_e), nmax = decf2(g_negmax_e);
        float a = 1.0f / (nmax - nmin + 1e-8f);
        float b = 1.0f - nmin * a;
        lse = logf(spd + a * tn + b * sn);
    }
    lse = __shfl_sync(0xFFFFFFFFu, lse, (tid & 24), 32);   // broadcast from sub==0 of this group

    float vmin = decf2(g_pvmin_e), vmax = decf2(g_pvmax_e);
    float wmin = 1.0f - vmax, wmax = 1.0f - vmin;
    float inv = 1.0f / (wmax - wmin + 1e-8f);
    int idx = i * NPOS + sub;
    float pw = ((1.0f - pv[idx]) - wmin) * inv;
    float local = (g_pos_s[idx] - lse) * pw;

    __shared__ float red[256];
    red[tid] = local;
    __syncthreads();
    for (int s = 128; s > 0; s >>= 1) {
        if (tid < s) red[tid] += red[tid + s];
        __syncthreads();
    }
    if (tid == 0) g_fpart[blockIdx.x] = red[0];
}

__global__ void k_final2(float* __restrict__ out) {
    const int tid = threadIdx.x;               // 256 threads
    float v = g_fpart[tid];
    #pragma unroll
    for (int o = 16; o > 0; o >>= 1) v += __shfl_xor_sync(0xFFFFFFFFu, v, o);
    __shared__ float ws[8];
    if ((tid & 31) == 0) ws[tid >> 5] = v;
    __syncthreads();
    if (tid == 0) {
        float s = 0.f;
        #pragma unroll
        for (int u = 0; u < 8; u++) s += ws[u];
        out[0] = -s * (1.0f / (float)(NB * NPOS));
    }
}

// ---------------- launch ----------------
extern "C" void kernel_launch(void* const* d_in, const int* in_sizes, int n_in,
                              void* d_out, int out_size) {
    const float* emb  = (const float*)d_in[0];
    const float* pv   = (const float*)d_in[1];
    const float* temp = (const float*)d_in[2];
    float* out = (float*)d_out;

    const int SMEM = 3 * TILE_A + 128 * 3 * 8 * 4;   // 215040
    cudaFuncSetAttribute(k_sim, cudaFuncAttributeMaxDynamicSharedMemorySize, SMEM);

    k_norm<<<NB, ND>>>(emb, temp);
    k_zpv<<<(NSLOT * NB) / 1024, 1024>>>(pv);
    k_sim<<<128, NTHREADS, SMEM>>>();
    k_lse<<<NB / 32, 256>>>(pv);
    k_final2<<<1, 256>>>(out);
}